// round 1
// baseline (speedup 1.0000x reference)
#include <cuda_runtime.h>

// ---------------------------------------------------------------------------
// MoE grouped GEMM, fp32 SIMT baseline.
// out[i] = weight[gate[i]] @ inp[i]
//   inp:    [65536, 512] f32
//   gate:   [65536]      i32 (0..63)
//   weight: [64, 512, 512] f32
//   out:    [65536, 512] f32
//
// Pipeline (all launches graph-capturable, no allocations):
//   1. k_zero     : reset counters
//   2. k_hist     : per-expert token counts (smem histogram + merge)
//   3. k_build    : prefix sum + tile table (single thread; ~600 iters)
//   4. k_scatter  : stable-ish scatter of token ids into expert-grouped perm
//   5. k_gemm     : tiled GEMM per (tile, out-column-tile)
// ---------------------------------------------------------------------------

#define N_TOKENS 65536
#define D_IN     512
#define D_OUT    512
#define N_EXP    64

#define TM 128   // tokens per tile
#define TN 64    // output features per tile
#define BK 16    // k-slab
#define MAX_TILES 1024   // worst case: 65536/128 + 64 = 576

__device__ int g_counts[N_EXP];
__device__ int g_cursor[N_EXP];
__device__ int g_offsets[N_EXP];
__device__ int g_perm[N_TOKENS];
__device__ int g_tile_expert[MAX_TILES];
__device__ int g_tile_start[MAX_TILES];
__device__ int g_tile_rows[MAX_TILES];
__device__ int g_ntiles;

__global__ void k_zero() {
    int t = threadIdx.x;
    if (t < N_EXP) { g_counts[t] = 0; g_cursor[t] = 0; }
}

__global__ void k_hist(const int* __restrict__ gate) {
    __shared__ int h[N_EXP];
    int t = threadIdx.x;
    if (t < N_EXP) h[t] = 0;
    __syncthreads();
    for (int i = blockIdx.x * blockDim.x + t; i < N_TOKENS; i += gridDim.x * blockDim.x)
        atomicAdd(&h[gate[i]], 1);
    __syncthreads();
    if (t < N_EXP && h[t]) atomicAdd(&g_counts[t], h[t]);
}

__global__ void k_build() {
    if (threadIdx.x == 0 && blockIdx.x == 0) {
        int off = 0, nt = 0;
        for (int e = 0; e < N_EXP; e++) {
            g_offsets[e] = off;
            int c = g_counts[e];
            for (int s = 0; s < c; s += TM) {
                g_tile_expert[nt] = e;
                g_tile_start[nt]  = off + s;
                g_tile_rows[nt]   = min(TM, c - s);
                nt++;
            }
            off += c;
        }
        g_ntiles = nt;
    }
}

__global__ void k_scatter(const int* __restrict__ gate) {
    int i = blockIdx.x * blockDim.x + threadIdx.x;
    if (i < N_TOKENS) {
        int e = gate[i];
        int pos = g_offsets[e] + atomicAdd(&g_cursor[e], 1);
        g_perm[pos] = i;
    }
}

// 256 threads; 16x16 thread grid; each thread computes 8 tokens x 4 outs.
__global__ __launch_bounds__(256) void k_gemm(const float* __restrict__ inp,
                                              const float* __restrict__ weight,
                                              float* __restrict__ out) {
    int tile = blockIdx.x;
    if (tile >= g_ntiles) return;
    int e     = g_tile_expert[tile];
    int start = g_tile_start[tile];
    int nrows = g_tile_rows[tile];
    int otile = blockIdx.y * TN;

    __shared__ float As[BK][TM];   // A transposed: As[k][token]
    __shared__ float Bs[BK][TN];   // Bs[k][out]
    __shared__ int   rows_s[TM];

    int tid = threadIdx.x;
    if (tid < TM) rows_s[tid] = (tid < nrows) ? g_perm[start + tid] : -1;
    __syncthreads();

    int tx = tid & 15;   // out-col group   (4 cols each)
    int ty = tid >> 4;   // token-row group (8 rows each)

    float acc[8][4];
    #pragma unroll
    for (int i = 0; i < 8; i++)
        #pragma unroll
        for (int j = 0; j < 4; j++) acc[i][j] = 0.f;

    const float* wbase = weight + ((size_t)e * D_OUT + otile) * D_IN;

    for (int kk = 0; kk < D_IN; kk += BK) {
        // --- load A tile: 128 rows x 16 k = 512 float4, 2 per thread,
        //     4 consecutive lanes cover one row's 64B (coalesced per row) ---
        #pragma unroll
        for (int l = 0; l < 2; l++) {
            int lid = tid + l * 256;      // 0..511
            int r   = lid >> 2;           // 0..127
            int k4  = lid & 3;            // 0..3 (float4 index within BK)
            int row = rows_s[r];
            float4 v = make_float4(0.f, 0.f, 0.f, 0.f);
            if (row >= 0)
                v = *(const float4*)(inp + (size_t)row * D_IN + kk + k4 * 4);
            As[k4 * 4 + 0][r] = v.x;
            As[k4 * 4 + 1][r] = v.y;
            As[k4 * 4 + 2][r] = v.z;
            As[k4 * 4 + 3][r] = v.w;
        }
        // --- load B tile: 64 outs x 16 k = 256 float4, 1 per thread ---
        {
            int o  = tid >> 2;            // 0..63
            int k4 = tid & 3;
            float4 v = *(const float4*)(wbase + (size_t)o * D_IN + kk + k4 * 4);
            Bs[k4 * 4 + 0][o] = v.x;
            Bs[k4 * 4 + 1][o] = v.y;
            Bs[k4 * 4 + 2][o] = v.z;
            Bs[k4 * 4 + 3][o] = v.w;
        }
        __syncthreads();

        #pragma unroll
        for (int k = 0; k < BK; k++) {
            float4 a0 = *(const float4*)&As[k][ty * 8];
            float4 a1 = *(const float4*)&As[k][ty * 8 + 4];
            float4 bv = *(const float4*)&Bs[k][tx * 4];
            float a[8] = {a0.x, a0.y, a0.z, a0.w, a1.x, a1.y, a1.z, a1.w};
            float b[4] = {bv.x, bv.y, bv.z, bv.w};
            #pragma unroll
            for (int i = 0; i < 8; i++)
                #pragma unroll
                for (int j = 0; j < 4; j++)
                    acc[i][j] = fmaf(a[i], b[j], acc[i][j]);
        }
        __syncthreads();
    }

    #pragma unroll
    for (int i = 0; i < 8; i++) {
        int r = ty * 8 + i;
        int row = rows_s[r];
        if (row >= 0) {
            float4 v = make_float4(acc[i][0], acc[i][1], acc[i][2], acc[i][3]);
            *(float4*)(out + (size_t)row * D_OUT + otile + tx * 4) = v;
        }
    }
}

extern "C" void kernel_launch(void* const* d_in, const int* in_sizes, int n_in,
                              void* d_out, int out_size) {
    const float* inp    = (const float*)d_in[0];
    const int*   gate   = (const int*)d_in[1];
    const float* weight = (const float*)d_in[2];
    float*       out    = (float*)d_out;

    k_zero<<<1, 64>>>();
    k_hist<<<256, 256>>>(gate);
    k_build<<<1, 32>>>();
    k_scatter<<<256, 256>>>(gate);
    // 640 tile slots (>= worst case 576); y = 8 output-column tiles
    dim3 grid(640, D_OUT / TN);
    k_gemm<<<grid, 256>>>(inp, weight, out);
}

// round 3
// speedup vs baseline: 1.6300x; 1.6300x over previous
#include <cuda_runtime.h>
#include <cstdint>

// ---------------------------------------------------------------------------
// MoE grouped GEMM via legacy mma.sync tf32 (sm_80+ path; tcgen05 is not
// available because the harness compiles PTX at target sm_103 without 'a').
// out[i] = weight[gate[i]] @ inp[i]
//   inp: [65536,512] f32, gate: [65536] i32, weight: [64,512,512] f32
// ---------------------------------------------------------------------------

#define N_TOKENS 65536
#define D_IN     512
#define D_OUT    512
#define N_EXP    64

#define TM 128
#define TN 128
#define BK 32
#define NITER (D_IN / BK)       // 16
#define MAX_TILES 1024
#define STRIDE 36               // padded floats per smem row (conflict-free)

#define A_BYTES (TM * STRIDE * 4)       // 18432
#define SM_ROWS 0
#define SM_A    1024
#define SM_B    (SM_A + 2 * A_BYTES)    // 37888
#define SMEM_TOTAL (SM_B + 2 * A_BYTES) // 74752

__device__ int g_counts[N_EXP];
__device__ int g_cursor[N_EXP];
__device__ int g_offsets[N_EXP];
__device__ int g_perm[N_TOKENS];
__device__ int g_tile_expert[MAX_TILES];
__device__ int g_tile_start[MAX_TILES];
__device__ int g_tile_rows[MAX_TILES];
__device__ int g_ntiles;

// ---------------- prep kernels ----------------
__global__ void k_zero() {
    int t = threadIdx.x;
    if (t < N_EXP) { g_counts[t] = 0; g_cursor[t] = 0; }
}

__global__ void k_hist(const int4* __restrict__ gate4) {
    __shared__ int h[N_EXP];
    int t = threadIdx.x;
    if (t < N_EXP) h[t] = 0;
    __syncthreads();
    int4 g = gate4[blockIdx.x * blockDim.x + t];
    atomicAdd(&h[g.x], 1); atomicAdd(&h[g.y], 1);
    atomicAdd(&h[g.z], 1); atomicAdd(&h[g.w], 1);
    __syncthreads();
    if (t < N_EXP && h[t]) atomicAdd(&g_counts[t], h[t]);
}

__global__ void k_build() {   // 64 threads, shuffle prefix sums
    __shared__ int ws[2], wt[2];
    int e = threadIdx.x;
    int c = g_counts[e];
    int x = c;
    #pragma unroll
    for (int d = 1; d < 32; d <<= 1) {
        int v = __shfl_up_sync(0xFFFFFFFFu, x, d);
        if ((e & 31) >= d) x += v;
    }
    if ((e & 31) == 31) ws[e >> 5] = x;
    __syncthreads();
    int off = x - c + ((e >= 32) ? ws[0] : 0);
    g_offsets[e] = off;

    int nt = (c + TM - 1) / TM;
    int y = nt;
    #pragma unroll
    for (int d = 1; d < 32; d <<= 1) {
        int v = __shfl_up_sync(0xFFFFFFFFu, y, d);
        if ((e & 31) >= d) y += v;
    }
    if ((e & 31) == 31) wt[e >> 5] = y;
    __syncthreads();
    int tbase = y - nt + ((e >= 32) ? wt[0] : 0);
    for (int s = 0, i = 0; s < c; s += TM, i++) {
        g_tile_expert[tbase + i] = e;
        g_tile_start[tbase + i]  = off + s;
        g_tile_rows[tbase + i]   = min(TM, c - s);
    }
    if (e == 63) g_ntiles = tbase + nt;
}

__global__ void k_scatter(const int* __restrict__ gate) {
    __shared__ int lh[N_EXP], lb[N_EXP];
    int t = threadIdx.x;
    if (t < N_EXP) lh[t] = 0;
    __syncthreads();
    int base = blockIdx.x * 1024;
    int4 g = ((const int4*)(gate + base))[t];
    int r0 = atomicAdd(&lh[g.x], 1);
    int r1 = atomicAdd(&lh[g.y], 1);
    int r2 = atomicAdd(&lh[g.z], 1);
    int r3 = atomicAdd(&lh[g.w], 1);
    __syncthreads();
    if (t < N_EXP) {
        int c = lh[t];
        lb[t] = c ? (g_offsets[t] + atomicAdd(&g_cursor[t], c)) : 0;
    }
    __syncthreads();
    int tok = base + t * 4;
    g_perm[lb[g.x] + r0] = tok + 0;
    g_perm[lb[g.y] + r1] = tok + 1;
    g_perm[lb[g.z] + r2] = tok + 2;
    g_perm[lb[g.w] + r3] = tok + 3;
}

// ---------------- GEMM helpers ----------------
__device__ __forceinline__ uint32_t tf32_rna(float x) {
    uint32_t r; asm("cvt.rna.tf32.f32 %0, %1;" : "=r"(r) : "f"(x)); return r;
}
__device__ __forceinline__ void mma_16n8k8(float* d, const uint32_t* a, const uint32_t* b) {
    asm volatile(
        "mma.sync.aligned.m16n8k8.row.col.f32.tf32.tf32.f32 "
        "{%0,%1,%2,%3}, {%4,%5,%6,%7}, {%8,%9}, {%0,%1,%2,%3};"
        : "+f"(d[0]), "+f"(d[1]), "+f"(d[2]), "+f"(d[3])
        : "r"(a[0]), "r"(a[1]), "r"(a[2]), "r"(a[3]), "r"(b[0]), "r"(b[1]));
}

// ---------------- tensor-core GEMM ----------------
__global__ __launch_bounds__(256, 1) void k_gemm(const float* __restrict__ inp,
                                                 const float* __restrict__ weight,
                                                 float* __restrict__ out) {
    int tile = blockIdx.x;
    if (tile >= g_ntiles) return;
    int e     = g_tile_expert[tile];
    int start = g_tile_start[tile];
    int nrows = g_tile_rows[tile];
    int otile = blockIdx.y * TN;

    extern __shared__ char smem[];
    int* rows_s = (int*)(smem + SM_ROWS);
    uint32_t* Asm[2] = {(uint32_t*)(smem + SM_A), (uint32_t*)(smem + SM_A + A_BYTES)};
    uint32_t* Bsm[2] = {(uint32_t*)(smem + SM_B), (uint32_t*)(smem + SM_B + A_BYTES)};

    int tid = threadIdx.x;
    int wid = tid >> 5, lid = tid & 31;
    int wm = wid & 1, wn = wid >> 1;     // warp tile: rows wm*64, cols wn*32
    int g  = lid >> 2, c = lid & 3;

    if (tid < TM) rows_s[tid] = (tid < nrows) ? g_perm[start + tid] : -1;
    __syncthreads();

    // Global load slots: row = tid>>1, 16-float half = tid&1
    int r    = tid >> 1, half = tid & 1;
    int arow = rows_s[r];
    const float* ap = inp + (size_t)((arow < 0) ? 0 : arow) * D_IN + half * 16;
    const float* bp = weight + ((size_t)e * D_OUT + otile + r) * D_IN + half * 16;
    int sdst = r * STRIDE + half * 16;   // smem float offset for stores

    float acc[4][4][4];
    #pragma unroll
    for (int mi = 0; mi < 4; mi++)
        #pragma unroll
        for (int ni = 0; ni < 4; ni++)
            #pragma unroll
            for (int q = 0; q < 4; q++) acc[mi][ni][q] = 0.f;

    float4 la[4], lb[4];

    // prologue: chunk 0
    #pragma unroll
    for (int q = 0; q < 4; q++) {
        la[q] = (arow >= 0) ? *(const float4*)(ap + q * 4) : make_float4(0.f, 0.f, 0.f, 0.f);
        lb[q] = *(const float4*)(bp + q * 4);
    }
    #pragma unroll
    for (int q = 0; q < 4; q++) {
        uint32_t* A = Asm[0] + sdst + q * 4;
        A[0] = tf32_rna(la[q].x); A[1] = tf32_rna(la[q].y);
        A[2] = tf32_rna(la[q].z); A[3] = tf32_rna(la[q].w);
        uint32_t* B = Bsm[0] + sdst + q * 4;
        B[0] = tf32_rna(lb[q].x); B[1] = tf32_rna(lb[q].y);
        B[2] = tf32_rna(lb[q].z); B[3] = tf32_rna(lb[q].w);
    }
    __syncthreads();

    for (int it = 0; it < NITER; it++) {
        int buf = it & 1;
        if (it + 1 < NITER) {
            int kk = (it + 1) * BK;
            #pragma unroll
            for (int q = 0; q < 4; q++) {
                la[q] = (arow >= 0) ? *(const float4*)(ap + kk + q * 4)
                                    : make_float4(0.f, 0.f, 0.f, 0.f);
                lb[q] = *(const float4*)(bp + kk + q * 4);
            }
        }

        const uint32_t* A = Asm[buf];
        const uint32_t* B = Bsm[buf];
        #pragma unroll
        for (int ks = 0; ks < 4; ks++) {
            int k0 = ks * 8 + c;
            uint32_t af[4][4], bf[4][2];
            #pragma unroll
            for (int mi = 0; mi < 4; mi++) {
                int base = (wm * 64 + mi * 16 + g) * STRIDE + k0;
                af[mi][0] = A[base];
                af[mi][1] = A[base + 8 * STRIDE];
                af[mi][2] = A[base + 4];
                af[mi][3] = A[base + 8 * STRIDE + 4];
            }
            #pragma unroll
            for (int ni = 0; ni < 4; ni++) {
                int base = (wn * 32 + ni * 8 + g) * STRIDE + k0;
                bf[ni][0] = B[base];
                bf[ni][1] = B[base + 4];
            }
            #pragma unroll
            for (int mi = 0; mi < 4; mi++)
                #pragma unroll
                for (int ni = 0; ni < 4; ni++)
                    mma_16n8k8(acc[mi][ni], af[mi], bf[ni]);
        }

        if (it + 1 < NITER) {
            int nbuf = buf ^ 1;
            #pragma unroll
            for (int q = 0; q < 4; q++) {
                uint32_t* Ad = Asm[nbuf] + sdst + q * 4;
                Ad[0] = tf32_rna(la[q].x); Ad[1] = tf32_rna(la[q].y);
                Ad[2] = tf32_rna(la[q].z); Ad[3] = tf32_rna(la[q].w);
                uint32_t* Bd = Bsm[nbuf] + sdst + q * 4;
                Bd[0] = tf32_rna(lb[q].x); Bd[1] = tf32_rna(lb[q].y);
                Bd[2] = tf32_rna(lb[q].z); Bd[3] = tf32_rna(lb[q].w);
            }
            __syncthreads();
        }
    }

    // Epilogue: thread (g,c) owns rows g/g+8, cols 2c/2c+1 of each m16n8 tile
    #pragma unroll
    for (int mi = 0; mi < 4; mi++) {
        int r0 = wm * 64 + mi * 16 + g;
        int row0 = rows_s[r0];
        int row1 = rows_s[r0 + 8];
        #pragma unroll
        for (int ni = 0; ni < 4; ni++) {
            int col = otile + wn * 32 + ni * 8 + 2 * c;
            if (row0 >= 0)
                *(float2*)(out + (size_t)row0 * D_OUT + col) =
                    make_float2(acc[mi][ni][0], acc[mi][ni][1]);
            if (row1 >= 0)
                *(float2*)(out + (size_t)row1 * D_OUT + col) =
                    make_float2(acc[mi][ni][2], acc[mi][ni][3]);
        }
    }
}

extern "C" void kernel_launch(void* const* d_in, const int* in_sizes, int n_in,
                              void* d_out, int out_size) {
    const float* inp    = (const float*)d_in[0];
    const int*   gate   = (const int*)d_in[1];
    const float* weight = (const float*)d_in[2];
    float*       out    = (float*)d_out;

    cudaFuncSetAttribute(k_gemm, cudaFuncAttributeMaxDynamicSharedMemorySize, SMEM_TOTAL);

    k_zero<<<1, 64>>>();
    k_hist<<<N_TOKENS / (256 * 4), 256>>>((const int4*)gate);
    k_build<<<1, 64>>>();
    k_scatter<<<N_TOKENS / 1024, 256>>>(gate);
    dim3 grid(640, D_OUT / TN);
    k_gemm<<<grid, 256, SMEM_TOTAL>>>(inp, weight, out);
}

// round 5
// speedup vs baseline: 3.4207x; 2.0986x over previous
#include <cuda_runtime.h>
#include <cstdint>

// ---------------------------------------------------------------------------
// MoE grouped GEMM, mma.sync tf32 + cp.async 3-stage pipeline, 2 CTAs/SM.
// RNA rounding applied to fragments in registers (cp.async can't pre-round).
// out[i] = weight[gate[i]] @ inp[i]
//   inp: [65536,512] f32, gate: [65536] i32, weight: [64,512,512] f32
// ---------------------------------------------------------------------------

#define N_TOKENS 65536
#define D_IN     512
#define D_OUT    512
#define N_EXP    64

#define TM 128
#define TN 128
#define BK 32
#define NITER (D_IN / BK)       // 16
#define NSTAGE 3
#define MAX_TILES 1024
#define STRIDE 36               // floats per smem row (144B, conflict-free LDS)

#define ROWSTEP     (32 * STRIDE * 4)        // smem bytes per 32-row group
#define TILE_BYTES  (TM * STRIDE * 4)        // 18432 per operand
#define STAGE_BYTES (2 * TILE_BYTES)         // A then B
#define SM_ROWS 0
#define SM_A    1024
#define SMEM_TOTAL (SM_A + NSTAGE * STAGE_BYTES)   // 111616

__device__ int g_counts[N_EXP];
__device__ int g_cursor[N_EXP];
__device__ int g_offsets[N_EXP];
__device__ int g_perm[N_TOKENS];
__device__ int g_tile_expert[MAX_TILES];
__device__ int g_tile_start[MAX_TILES];
__device__ int g_tile_rows[MAX_TILES];
__device__ int g_ntiles;

// ---------------- prep kernels ----------------
__global__ void k_zero() {
    int t = threadIdx.x;
    if (t < N_EXP) { g_counts[t] = 0; g_cursor[t] = 0; }
}

__global__ void k_hist(const int4* __restrict__ gate4) {
    __shared__ int h[N_EXP];
    int t = threadIdx.x;
    if (t < N_EXP) h[t] = 0;
    __syncthreads();
    int4 g = gate4[blockIdx.x * blockDim.x + t];
    atomicAdd(&h[g.x], 1); atomicAdd(&h[g.y], 1);
    atomicAdd(&h[g.z], 1); atomicAdd(&h[g.w], 1);
    __syncthreads();
    if (t < N_EXP && h[t]) atomicAdd(&g_counts[t], h[t]);
}

__global__ void k_build() {
    __shared__ int ws[2], wt[2];
    int e = threadIdx.x;
    int c = g_counts[e];
    int x = c;
    #pragma unroll
    for (int d = 1; d < 32; d <<= 1) {
        int v = __shfl_up_sync(0xFFFFFFFFu, x, d);
        if ((e & 31) >= d) x += v;
    }
    if ((e & 31) == 31) ws[e >> 5] = x;
    __syncthreads();
    int off = x - c + ((e >= 32) ? ws[0] : 0);
    g_offsets[e] = off;

    int nt = (c + TM - 1) / TM;
    int y = nt;
    #pragma unroll
    for (int d = 1; d < 32; d <<= 1) {
        int v = __shfl_up_sync(0xFFFFFFFFu, y, d);
        if ((e & 31) >= d) y += v;
    }
    if ((e & 31) == 31) wt[e >> 5] = y;
    __syncthreads();
    int tbase = y - nt + ((e >= 32) ? wt[0] : 0);
    for (int s = 0, i = 0; s < c; s += TM, i++) {
        g_tile_expert[tbase + i] = e;
        g_tile_start[tbase + i]  = off + s;
        g_tile_rows[tbase + i]   = min(TM, c - s);
    }
    if (e == 63) g_ntiles = tbase + nt;
}

__global__ void k_scatter(const int* __restrict__ gate) {
    __shared__ int lh[N_EXP], lb[N_EXP];
    int t = threadIdx.x;
    if (t < N_EXP) lh[t] = 0;
    __syncthreads();
    int base = blockIdx.x * 1024;
    int4 g = ((const int4*)(gate + base))[t];
    int r0 = atomicAdd(&lh[g.x], 1);
    int r1 = atomicAdd(&lh[g.y], 1);
    int r2 = atomicAdd(&lh[g.z], 1);
    int r3 = atomicAdd(&lh[g.w], 1);
    __syncthreads();
    if (t < N_EXP) {
        int c = lh[t];
        lb[t] = c ? (g_offsets[t] + atomicAdd(&g_cursor[t], c)) : 0;
    }
    __syncthreads();
    int tok = base + t * 4;
    g_perm[lb[g.x] + r0] = tok + 0;
    g_perm[lb[g.y] + r1] = tok + 1;
    g_perm[lb[g.z] + r2] = tok + 2;
    g_perm[lb[g.w] + r3] = tok + 3;
}

// ---------------- GEMM helpers ----------------
__device__ __forceinline__ uint32_t smem_u32(const void* p) {
    uint32_t a;
    asm("{ .reg .u64 t; cvta.to.shared.u64 t, %1; cvt.u32.u64 %0, t; }" : "=r"(a) : "l"(p));
    return a;
}
__device__ __forceinline__ void cp16(uint32_t dst, const void* src, uint32_t srcsize) {
    asm volatile("cp.async.cg.shared.global [%0], [%1], 16, %2;"
                 :: "r"(dst), "l"(src), "r"(srcsize) : "memory");
}
__device__ __forceinline__ void rnd(uint32_t& r) {
    asm("cvt.rna.tf32.f32 %0, %1;" : "=r"(r) : "f"(__uint_as_float(r)));
}
__device__ __forceinline__ void mma_16n8k8(float* d, const uint32_t* a, const uint32_t* b) {
    asm volatile(
        "mma.sync.aligned.m16n8k8.row.col.f32.tf32.tf32.f32 "
        "{%0,%1,%2,%3}, {%4,%5,%6,%7}, {%8,%9}, {%0,%1,%2,%3};"
        : "+f"(d[0]), "+f"(d[1]), "+f"(d[2]), "+f"(d[3])
        : "r"(a[0]), "r"(a[1]), "r"(a[2]), "r"(a[3]), "r"(b[0]), "r"(b[1]));
}

// ---------------- tensor-core GEMM ----------------
__global__ __launch_bounds__(256, 2) void k_gemm(const float* __restrict__ inp,
                                                 const float* __restrict__ weight,
                                                 float* __restrict__ out) {
    int tile = blockIdx.x;
    if (tile >= g_ntiles) return;
    int e     = g_tile_expert[tile];
    int start = g_tile_start[tile];
    int nrows = g_tile_rows[tile];
    int otile = blockIdx.y * TN;

    extern __shared__ char smem[];
    uint32_t sb = smem_u32(smem);
    int* rows_s = (int*)(smem + SM_ROWS);

    int tid = threadIdx.x;
    int wid = tid >> 5, lid = tid & 31;
    int wm = wid & 1, wn = wid >> 1;       // warp tile: rows wm*64, cols wn*32
    int g  = lid >> 2, c = lid & 3;

    if (tid < TM) rows_s[tid] = (tid < nrows) ? g_perm[start + tid] : -1;
    __syncthreads();

    // cp.async slots: thread covers rows row0 + l*32 (l=0..3), 16B segment seg.
    int row0 = tid >> 3, seg = tid & 7;
    const float* asrc[4]; uint32_t asz[4];
    #pragma unroll
    for (int l = 0; l < 4; l++) {
        int tok = rows_s[row0 + l * 32];
        asz[l]  = (tok >= 0) ? 16u : 0u;
        asrc[l] = inp + (size_t)((tok < 0) ? 0 : tok) * D_IN + seg * 4;
    }
    const float* bsrc0 = weight + ((size_t)e * D_OUT + otile + row0) * D_IN + seg * 4;
    uint32_t adst0 = sb + SM_A + row0 * (STRIDE * 4) + seg * 16;
    uint32_t bdst0 = adst0 + TILE_BYTES;

    float acc[4][4][4];
    #pragma unroll
    for (int mi = 0; mi < 4; mi++)
        #pragma unroll
        for (int ni = 0; ni < 4; ni++)
            #pragma unroll
            for (int q = 0; q < 4; q++) acc[mi][ni][q] = 0.f;

    // Prologue: stages 0 and 1
    #pragma unroll
    for (int st = 0; st < 2; st++) {
        uint32_t so = st * STAGE_BYTES;
        int kk = st * BK;
        #pragma unroll
        for (int l = 0; l < 4; l++) {
            cp16(adst0 + so + l * ROWSTEP, asrc[l] + kk, asz[l]);
            cp16(bdst0 + so + l * ROWSTEP, bsrc0 + kk + l * 32 * D_IN, 16u);
        }
        asm volatile("cp.async.commit_group;" ::: "memory");
    }

    for (int it = 0; it < NITER; it++) {
        asm volatile("cp.async.wait_group 1;" ::: "memory");
        __syncthreads();

        if (it + 2 < NITER) {
            uint32_t so = ((it + 2) % NSTAGE) * STAGE_BYTES;
            int kk = (it + 2) * BK;
            #pragma unroll
            for (int l = 0; l < 4; l++) {
                cp16(adst0 + so + l * ROWSTEP, asrc[l] + kk, asz[l]);
                cp16(bdst0 + so + l * ROWSTEP, bsrc0 + kk + l * 32 * D_IN, 16u);
            }
            asm volatile("cp.async.commit_group;" ::: "memory");
        }

        uint32_t so = (it % NSTAGE) * STAGE_BYTES;
        const uint32_t* A = (const uint32_t*)(smem + SM_A + so);
        const uint32_t* B = (const uint32_t*)(smem + SM_A + so + TILE_BYTES);
        #pragma unroll
        for (int ks = 0; ks < 4; ks++) {
            int k0 = ks * 8 + c;
            uint32_t af[4][4], bf[4][2];
            #pragma unroll
            for (int mi = 0; mi < 4; mi++) {
                int base = (wm * 64 + mi * 16 + g) * STRIDE + k0;
                af[mi][0] = A[base];
                af[mi][1] = A[base + 8 * STRIDE];
                af[mi][2] = A[base + 4];
                af[mi][3] = A[base + 8 * STRIDE + 4];
                rnd(af[mi][0]); rnd(af[mi][1]); rnd(af[mi][2]); rnd(af[mi][3]);
            }
            #pragma unroll
            for (int ni = 0; ni < 4; ni++) {
                int base = (wn * 32 + ni * 8 + g) * STRIDE + k0;
                bf[ni][0] = B[base];
                bf[ni][1] = B[base + 4];
                rnd(bf[ni][0]); rnd(bf[ni][1]);
            }
            #pragma unroll
            for (int mi = 0; mi < 4; mi++)
                #pragma unroll
                for (int ni = 0; ni < 4; ni++)
                    mma_16n8k8(acc[mi][ni], af[mi], bf[ni]);
        }
    }

    // Epilogue: thread (g,c) owns rows g/g+8, cols 2c/2c+1 of each m16n8 tile
    #pragma unroll
    for (int mi = 0; mi < 4; mi++) {
        int r0 = wm * 64 + mi * 16 + g;
        int row0e = rows_s[r0];
        int row1e = rows_s[r0 + 8];
        #pragma unroll
        for (int ni = 0; ni < 4; ni++) {
            int col = otile + wn * 32 + ni * 8 + 2 * c;
            if (row0e >= 0)
                *(float2*)(out + (size_t)row0e * D_OUT + col) =
                    make_float2(acc[mi][ni][0], acc[mi][ni][1]);
            if (row1e >= 0)
                *(float2*)(out + (size_t)row1e * D_OUT + col) =
                    make_float2(acc[mi][ni][2], acc[mi][ni][3]);
        }
    }
}

extern "C" void kernel_launch(void* const* d_in, const int* in_sizes, int n_in,
                              void* d_out, int out_size) {
    const float* inp    = (const float*)d_in[0];
    const int*   gate   = (const int*)d_in[1];
    const float* weight = (const float*)d_in[2];
    float*       out    = (float*)d_out;

    cudaFuncSetAttribute(k_gemm, cudaFuncAttributeMaxDynamicSharedMemorySize, SMEM_TOTAL);

    k_zero<<<1, 64>>>();
    k_hist<<<N_TOKENS / (256 * 4), 256>>>((const int4*)gate);
    k_build<<<1, 64>>>();
    k_scatter<<<N_TOKENS / 1024, 256>>>(gate);
    dim3 grid(640, D_OUT / TN);
    k_gemm<<<grid, 256, SMEM_TOTAL>>>(inp, weight, out);
}